// round 1
// baseline (speedup 1.0000x reference)
#include <cuda_runtime.h>
#include <cuda_bf16.h>

#define BATCH 4
#define NROWS 4096
#define DDIM  256

#define BM 128
#define BN 128
#define BK 8
#define TM 8
#define TN 8

// Scratch for row squared-norms (allocation-free per harness rules)
__device__ float g_X2[BATCH * NROWS];
__device__ float g_Y2[BATCH * NROWS];

// One warp per row: sum of squares over D=256 (2 float4 per lane)
__global__ void rbf_row_norms(const float* __restrict__ X,
                              const float* __restrict__ Y) {
    int warp = (blockIdx.x * blockDim.x + threadIdx.x) >> 5;
    int lane = threadIdx.x & 31;
    int total = 2 * BATCH * NROWS;
    if (warp >= total) return;

    const float* src;
    float* dst;
    int row;
    if (warp < BATCH * NROWS) { src = X; dst = g_X2; row = warp; }
    else                      { src = Y; dst = g_Y2; row = warp - BATCH * NROWS; }

    const float4* p = (const float4*)(src + (size_t)row * DDIM);
    float s = 0.f;
#pragma unroll
    for (int i = 0; i < DDIM / 4 / 32; i++) {   // 2 iterations
        float4 v = p[lane + i * 32];
        s += v.x * v.x + v.y * v.y + v.z * v.z + v.w * v.w;
    }
#pragma unroll
    for (int o = 16; o > 0; o >>= 1)
        s += __shfl_down_sync(0xffffffffu, s, o);
    if (lane == 0) dst[row] = s;
}

// 128x128 tile, K-step 8, 8x8 micro-tile per thread, 256 threads.
// acc = X[n,:] . Y[m,:]; epilogue: exp(-(x2+y2-2*acc)/2), clamped at 0.
__global__ __launch_bounds__(256, 2)
void rbf_gemm_exp(const float* __restrict__ X,
                  const float* __restrict__ Y,
                  float* __restrict__ out) {
    __shared__ float As[BK][BM];   // As[k][n]
    __shared__ float Bs[BK][BN];   // Bs[k][m]

    int b = blockIdx.z;
    const float* Xb = X + (size_t)b * NROWS * DDIM;
    const float* Yb = Y + (size_t)b * NROWS * DDIM;
    float* Ob = out + (size_t)b * NROWS * NROWS;

    int n0 = blockIdx.y * BM;
    int m0 = blockIdx.x * BN;

    int tid  = threadIdx.x;
    int lrow = tid >> 1;            // 0..127 : row within tile for loads
    int lcol = (tid & 1) * 4;       // 0 or 4 : k-offset for float4 load
    int tx   = tid & 15;            // column group (m)
    int ty   = tid >> 4;            // row group (n)

    float acc[TM][TN] = {};

    for (int k0 = 0; k0 < DDIM; k0 += BK) {
        float4 av = *(const float4*)(Xb + (size_t)(n0 + lrow) * DDIM + k0 + lcol);
        float4 bv = *(const float4*)(Yb + (size_t)(m0 + lrow) * DDIM + k0 + lcol);

        __syncthreads();   // previous compute done before overwrite
        As[lcol + 0][lrow] = av.x;
        As[lcol + 1][lrow] = av.y;
        As[lcol + 2][lrow] = av.z;
        As[lcol + 3][lrow] = av.w;
        Bs[lcol + 0][lrow] = bv.x;
        Bs[lcol + 1][lrow] = bv.y;
        Bs[lcol + 2][lrow] = bv.z;
        Bs[lcol + 3][lrow] = bv.w;
        __syncthreads();

#pragma unroll
        for (int k = 0; k < BK; k++) {
            float a[TM], bb[TN];
#pragma unroll
            for (int i = 0; i < TM; i++) a[i] = As[k][ty * TM + i];
#pragma unroll
            for (int j = 0; j < TN; j++) bb[j] = Bs[k][tx * TN + j];
#pragma unroll
            for (int i = 0; i < TM; i++)
#pragma unroll
                for (int j = 0; j < TN; j++)
                    acc[i][j] = fmaf(a[i], bb[j], acc[i][j]);
        }
    }

    float xn[TM], ym[TN];
#pragma unroll
    for (int i = 0; i < TM; i++) xn[i] = g_X2[b * NROWS + n0 + ty * TM + i];
#pragma unroll
    for (int j = 0; j < TN; j++) ym[j] = g_Y2[b * NROWS + m0 + tx * TN + j];

#pragma unroll
    for (int i = 0; i < TM; i++) {
        float o[TN];
#pragma unroll
        for (int j = 0; j < TN; j++) {
            float d = xn[i] + ym[j] - 2.f * acc[i][j];
            d = fmaxf(d, 0.f);
            o[j] = __expf(-0.5f * d);
        }
        float* dst = Ob + (size_t)(n0 + ty * TM + i) * NROWS + m0 + tx * TN;
        *(float4*)(dst + 0) = make_float4(o[0], o[1], o[2], o[3]);
        *(float4*)(dst + 4) = make_float4(o[4], o[5], o[6], o[7]);
    }
}

extern "C" void kernel_launch(void* const* d_in, const int* in_sizes, int n_in,
                              void* d_out, int out_size) {
    const float* X = (const float*)d_in[0];
    const float* Y = (const float*)d_in[1];
    float* out = (float*)d_out;

    // Row norms: 2*B*N rows, one warp each
    int warps = 2 * BATCH * NROWS;
    int threads = 256;
    int blocks = (warps * 32 + threads - 1) / threads;
    rbf_row_norms<<<blocks, threads>>>(X, Y);

    dim3 grid(NROWS / BN, NROWS / BM, BATCH);
    rbf_gemm_exp<<<grid, 256>>>(X, Y, out);
}

// round 3
// speedup vs baseline: 4.4246x; 4.4246x over previous
#include <cuda_runtime.h>
#include <cuda_bf16.h>
#include <cstdint>

#define BATCH 4
#define NROWS 4096
#define DDIM  256

#define BM 128
#define BN 256
#define BK 64
#define NCHUNK (DDIM / BK)      // 4
#define THREADS 256

// stage: A 128x64 bf16 (16KB, 128B/row) + B 256x64 bf16 (32KB) = 48KB; 2 stages
#define A_STAGE_BYTES 16384
#define STAGE_BYTES   49152
#define SMEM_BYTES    (2 * STAGE_BYTES)

// ---------------- device scratch (allocation-free) ----------------
__device__ __nv_bfloat16 g_Xb[(size_t)BATCH * NROWS * DDIM];
__device__ __nv_bfloat16 g_Yb[(size_t)BATCH * NROWS * DDIM];
__device__ float g_X2[BATCH * NROWS];
__device__ float g_Y2[BATCH * NROWS];

// ---------------- PTX helpers (base ISA only: sm_80+) ----------------
__device__ __forceinline__ uint32_t smem_u32(const void* p) {
    uint32_t a;
    asm("{ .reg .u64 t; cvta.to.shared.u64 t, %1; cvt.u32.u64 %0, t; }" : "=r"(a) : "l"(p));
    return a;
}
__device__ __forceinline__ void cp_async16(uint32_t dst, const void* src) {
    asm volatile("cp.async.cg.shared.global [%0], [%1], 16;" :: "r"(dst), "l"(src));
}
#define CP_COMMIT()  asm volatile("cp.async.commit_group;" ::: "memory")
#define CP_WAIT(N)   asm volatile("cp.async.wait_group %0;" :: "n"(N) : "memory")

__device__ __forceinline__ void ldsm_x4(uint32_t& r0, uint32_t& r1, uint32_t& r2,
                                        uint32_t& r3, uint32_t addr) {
    asm volatile("ldmatrix.sync.aligned.m8n8.x4.shared.b16 {%0,%1,%2,%3}, [%4];"
                 : "=r"(r0), "=r"(r1), "=r"(r2), "=r"(r3) : "r"(addr));
}
__device__ __forceinline__ void mma_bf16(float* c, const uint32_t* a, const uint32_t* b) {
    asm volatile(
        "mma.sync.aligned.m16n8k16.row.col.f32.bf16.bf16.f32 "
        "{%0,%1,%2,%3}, {%4,%5,%6,%7}, {%8,%9}, {%0,%1,%2,%3};"
        : "+f"(c[0]), "+f"(c[1]), "+f"(c[2]), "+f"(c[3])
        : "r"(a[0]), "r"(a[1]), "r"(a[2]), "r"(a[3]), "r"(b[0]), "r"(b[1]));
}

// ---------------- prep: fp32 row norms + bf16 conversion ----------------
__global__ void rbf_prep(const float* __restrict__ X, const float* __restrict__ Y) {
    int warp = (blockIdx.x * blockDim.x + threadIdx.x) >> 5;
    int lane = threadIdx.x & 31;
    bool isY = warp >= BATCH * NROWS;
    int row = isY ? warp - BATCH * NROWS : warp;

    const float* src = (isY ? Y : X) + (size_t)row * DDIM;
    __nv_bfloat16* dst = (isY ? g_Yb : g_Xb) + (size_t)row * DDIM;

    float s = 0.f;
#pragma unroll
    for (int i = 0; i < 2; i++) {
        float4 v = ((const float4*)src)[lane + 32 * i];
        s += v.x * v.x + v.y * v.y + v.z * v.z + v.w * v.w;
        __nv_bfloat162 p0, p1;
        p0.x = __float2bfloat16(v.x); p0.y = __float2bfloat16(v.y);
        p1.x = __float2bfloat16(v.z); p1.y = __float2bfloat16(v.w);
        ((__nv_bfloat162*)dst)[2 * (lane + 32 * i) + 0] = p0;
        ((__nv_bfloat162*)dst)[2 * (lane + 32 * i) + 1] = p1;
    }
#pragma unroll
    for (int o = 16; o > 0; o >>= 1) s += __shfl_down_sync(0xffffffffu, s, o);
    if (lane == 0) (isY ? g_Y2 : g_X2)[row] = s;
}

// swizzled smem byte offset within a 128B-row tile: bits[6:4] ^= row%8
__device__ __forceinline__ uint32_t swz(int row, int colb) {
    return (uint32_t)(row * 128 + (colb ^ ((row & 7) << 4)));
}

// ---------------- main: mma.sync bf16 GEMM + fused RBF epilogue ----------------
__global__ __launch_bounds__(THREADS, 1)
void rbf_mma(float* __restrict__ out) {
    extern __shared__ char smem[];
    const int b  = blockIdx.z;
    const int j0 = blockIdx.x * BN;   // Y rows / out cols
    const int i0 = blockIdx.y * BM;   // X rows / out rows
    const int tid = threadIdx.x, wid = tid >> 5, lane = tid & 31;
    const int wm = wid >> 2, wn = wid & 3;   // 2 x 4 warp grid, 64x64 warp tile

    const uint32_t sbase = smem_u32(smem);
    const __nv_bfloat16* Xb = g_Xb + (size_t)(b * NROWS + i0) * DDIM;
    const __nv_bfloat16* Yb = g_Yb + (size_t)(b * NROWS + j0) * DDIM;

    // cp.async assignment: lin -> (row = lin>>3, 16B-chunk = lin&7)
    const int ld_row = 0, ld_chunk = 0; (void)ld_row; (void)ld_chunk;

    auto load_stage = [&](int c, int s) {
        uint32_t Ab = sbase + s * STAGE_BYTES;
        uint32_t Bb = Ab + A_STAGE_BYTES;
#pragma unroll
        for (int i = 0; i < 4; i++) {            // A: 1024 x 16B
            int lin = tid + i * 256;
            int row = lin >> 3, ch = lin & 7;
            cp_async16(Ab + swz(row, ch * 16),
                       Xb + (size_t)row * DDIM + c * BK + ch * 8);
        }
#pragma unroll
        for (int i = 0; i < 8; i++) {            // B: 2048 x 16B
            int lin = tid + i * 256;
            int row = lin >> 3, ch = lin & 7;
            cp_async16(Bb + swz(row, ch * 16),
                       Yb + (size_t)row * DDIM + c * BK + ch * 8);
        }
    };

    float acc[4][8][4] = {};    // [mt][nt][frag]

    load_stage(0, 0); CP_COMMIT();
    load_stage(1, 1); CP_COMMIT();

    // ldmatrix per-thread address components
    const int a_row_l = wm * 64 + (lane & 15);      // + mt*16
    const int a_colb  = (lane >> 4) * 16;           // + ks*32
    const int b_row_l = wn * 64 + (lane >> 4) * 8 + (lane & 7);  // + p*16
    const int b_colb  = ((lane >> 3) & 1) * 16;     // + ks*32

    for (int c = 0; c < NCHUNK; c++) {
        if (c == NCHUNK - 1) { CP_WAIT(0); } else { CP_WAIT(1); }
        __syncthreads();

        uint32_t Ab = sbase + (c & 1) * STAGE_BYTES;
        uint32_t Bb = Ab + A_STAGE_BYTES;

#pragma unroll
        for (int ks = 0; ks < 4; ks++) {
            uint32_t af[4][4], bf[4][4];
#pragma unroll
            for (int mt = 0; mt < 4; mt++) {
                int row = a_row_l + mt * 16;
                ldsm_x4(af[mt][0], af[mt][1], af[mt][2], af[mt][3],
                        Ab + swz(row, ks * 32 + a_colb));
            }
#pragma unroll
            for (int p = 0; p < 4; p++) {        // pair p covers n-tiles 2p,2p+1
                int row = b_row_l + p * 16;
                ldsm_x4(bf[p][0], bf[p][1], bf[p][2], bf[p][3],
                        Bb + swz(row, ks * 32 + b_colb));
            }
#pragma unroll
            for (int mt = 0; mt < 4; mt++)
#pragma unroll
                for (int nt = 0; nt < 8; nt++)
                    mma_bf16(acc[mt][nt], af[mt], &bf[nt >> 1][(nt & 1) * 2]);
        }

        __syncthreads();
        if (c + 2 < NCHUNK) { load_stage(c + 2, c & 1); CP_COMMIT(); }
    }

    // ---------------- epilogue ----------------
    // acc frag c0,c1: (row lane/4,     col 2(lane%4), +1)
    //          c2,c3: (row lane/4 + 8, col 2(lane%4), +1)
    const int er = lane >> 2;
    const int ec = 2 * (lane & 3);
    const float* X2 = g_X2 + b * NROWS + i0 + wm * 64;
    const float* Y2 = g_Y2 + b * NROWS + j0 + wn * 64;

#pragma unroll
    for (int mt = 0; mt < 4; mt++) {
        float x2a = X2[mt * 16 + er];
        float x2b = X2[mt * 16 + er + 8];
#pragma unroll
        for (int nt = 0; nt < 8; nt++) {
            float2 y2 = *(const float2*)(Y2 + nt * 8 + ec);
            float* a = acc[mt][nt];

            float d0 = fmaxf(x2a + y2.x - 2.f * a[0], 0.f);
            float d1 = fmaxf(x2a + y2.y - 2.f * a[1], 0.f);
            float d2 = fmaxf(x2b + y2.x - 2.f * a[2], 0.f);
            float d3 = fmaxf(x2b + y2.y - 2.f * a[3], 0.f);

            float2 o01, o23;
            o01.x = (d0 < 212.f) ? __expf(-0.5f * d0) : 0.f;
            o01.y = (d1 < 212.f) ? __expf(-0.5f * d1) : 0.f;
            o23.x = (d2 < 212.f) ? __expf(-0.5f * d2) : 0.f;
            o23.y = (d3 < 212.f) ? __expf(-0.5f * d3) : 0.f;

            size_t r0 = (size_t)(b * NROWS + i0 + wm * 64 + mt * 16 + er) * NROWS
                        + j0 + wn * 64 + nt * 8 + ec;
            *(float2*)(out + r0) = o01;
            *(float2*)(out + r0 + 8 * NROWS) = o23;
        }
    }
}

extern "C" void kernel_launch(void* const* d_in, const int* in_sizes, int n_in,
                              void* d_out, int out_size) {
    const float* X = (const float*)d_in[0];
    const float* Y = (const float*)d_in[1];
    float* out = (float*)d_out;

    cudaFuncSetAttribute(rbf_mma, cudaFuncAttributeMaxDynamicSharedMemorySize, SMEM_BYTES);

    rbf_prep<<<2 * BATCH * NROWS / 8, 256>>>(X, Y);

    dim3 grid(NROWS / BN, NROWS / BM, BATCH);   // (16, 32, 4)
    rbf_mma<<<grid, THREADS, SMEM_BYTES>>>(out);
}

// round 4
// speedup vs baseline: 5.0818x; 1.1485x over previous
#include <cuda_runtime.h>
#include <cuda_bf16.h>
#include <cstdint>

#define BATCH 4
#define NROWS 4096
#define DDIM  256

#define BM 128
#define BN 256
#define BK 64
#define NCHUNK (DDIM / BK)      // 4
#define THREADS 512

// stage: A 128x64 bf16 (16KB, 128B/row) + B 256x64 bf16 (32KB) = 48KB; 2 stages
#define A_STAGE_BYTES 16384
#define STAGE_BYTES   49152
#define SMEM_BYTES    (2 * STAGE_BYTES)

// ---------------- device scratch (allocation-free) ----------------
__device__ __nv_bfloat16 g_Xb[(size_t)BATCH * NROWS * DDIM];
__device__ __nv_bfloat16 g_Yb[(size_t)BATCH * NROWS * DDIM];
__device__ float g_X2[BATCH * NROWS];
__device__ float g_Y2[BATCH * NROWS];

// ---------------- PTX helpers (base ISA only: sm_80+) ----------------
__device__ __forceinline__ uint32_t smem_u32(const void* p) {
    uint32_t a;
    asm("{ .reg .u64 t; cvta.to.shared.u64 t, %1; cvt.u32.u64 %0, t; }" : "=r"(a) : "l"(p));
    return a;
}
__device__ __forceinline__ void cp_async16(uint32_t dst, const void* src) {
    asm volatile("cp.async.cg.shared.global [%0], [%1], 16;" :: "r"(dst), "l"(src));
}
#define CP_COMMIT()  asm volatile("cp.async.commit_group;" ::: "memory")
#define CP_WAIT(N)   asm volatile("cp.async.wait_group %0;" :: "n"(N) : "memory")

__device__ __forceinline__ void ldsm_x4(uint32_t& r0, uint32_t& r1, uint32_t& r2,
                                        uint32_t& r3, uint32_t addr) {
    asm volatile("ldmatrix.sync.aligned.m8n8.x4.shared.b16 {%0,%1,%2,%3}, [%4];"
                 : "=r"(r0), "=r"(r1), "=r"(r2), "=r"(r3) : "r"(addr));
}
__device__ __forceinline__ void mma_bf16(float* c, const uint32_t* a, const uint32_t* b) {
    asm volatile(
        "mma.sync.aligned.m16n8k16.row.col.f32.bf16.bf16.f32 "
        "{%0,%1,%2,%3}, {%4,%5,%6,%7}, {%8,%9}, {%0,%1,%2,%3};"
        : "+f"(c[0]), "+f"(c[1]), "+f"(c[2]), "+f"(c[3])
        : "r"(a[0]), "r"(a[1]), "r"(a[2]), "r"(a[3]), "r"(b[0]), "r"(b[1]));
}

// ---------------- prep: fp32 row norms + bf16 conversion ----------------
__global__ void rbf_prep(const float* __restrict__ X, const float* __restrict__ Y) {
    int warp = (blockIdx.x * blockDim.x + threadIdx.x) >> 5;
    int lane = threadIdx.x & 31;
    bool isY = warp >= BATCH * NROWS;
    int row = isY ? warp - BATCH * NROWS : warp;

    const float* src = (isY ? Y : X) + (size_t)row * DDIM;
    __nv_bfloat16* dst = (isY ? g_Yb : g_Xb) + (size_t)row * DDIM;

    float s = 0.f;
#pragma unroll
    for (int i = 0; i < 2; i++) {
        float4 v = ((const float4*)src)[lane + 32 * i];
        s += v.x * v.x + v.y * v.y + v.z * v.z + v.w * v.w;
        __nv_bfloat162 p0, p1;
        p0.x = __float2bfloat16(v.x); p0.y = __float2bfloat16(v.y);
        p1.x = __float2bfloat16(v.z); p1.y = __float2bfloat16(v.w);
        ((__nv_bfloat162*)dst)[2 * (lane + 32 * i) + 0] = p0;
        ((__nv_bfloat162*)dst)[2 * (lane + 32 * i) + 1] = p1;
    }
#pragma unroll
    for (int o = 16; o > 0; o >>= 1) s += __shfl_down_sync(0xffffffffu, s, o);
    if (lane == 0) (isY ? g_Y2 : g_X2)[row] = s;
}

// swizzled smem byte offset within a 128B-row tile: bits[6:4] ^= row%8
__device__ __forceinline__ uint32_t swz(int row, int colb) {
    return (uint32_t)(row * 128 + (colb ^ ((row & 7) << 4)));
}

// ---------------- main: mma.sync bf16 GEMM + fused RBF epilogue ----------------
// 512 threads = 16 warps as 2 (m) x 8 (n); warp tile 64x32.
__global__ __launch_bounds__(THREADS, 1)
void rbf_mma(float* __restrict__ out) {
    extern __shared__ char smem[];
    const int b  = blockIdx.z;
    const int j0 = blockIdx.x * BN;   // Y rows / out cols
    const int i0 = blockIdx.y * BM;   // X rows / out rows
    const int tid = threadIdx.x, wid = tid >> 5, lane = tid & 31;
    const int wm = wid >> 3, wn = wid & 7;   // 2 x 8 warp grid, 64x32 warp tile

    const uint32_t sbase = smem_u32(smem);
    const __nv_bfloat16* Xb = g_Xb + (size_t)(b * NROWS + i0) * DDIM;
    const __nv_bfloat16* Yb = g_Yb + (size_t)(b * NROWS + j0) * DDIM;

    auto load_stage = [&](int c, int s) {
        uint32_t Ab = sbase + s * STAGE_BYTES;
        uint32_t Bb = Ab + A_STAGE_BYTES;
#pragma unroll
        for (int i = 0; i < 2; i++) {            // A: 1024 x 16B
            int lin = tid + i * 512;
            int row = lin >> 3, ch = lin & 7;
            cp_async16(Ab + swz(row, ch * 16),
                       Xb + (size_t)row * DDIM + c * BK + ch * 8);
        }
#pragma unroll
        for (int i = 0; i < 4; i++) {            // B: 2048 x 16B
            int lin = tid + i * 512;
            int row = lin >> 3, ch = lin & 7;
            cp_async16(Bb + swz(row, ch * 16),
                       Yb + (size_t)row * DDIM + c * BK + ch * 8);
        }
    };

    float acc[4][4][4] = {};    // [mt][nt][frag]

    load_stage(0, 0); CP_COMMIT();
    load_stage(1, 1); CP_COMMIT();

    // ldmatrix per-thread address components
    const int a_row_l = wm * 64 + (lane & 15);                    // + mt*16
    const int a_colb  = (lane >> 4) * 16;                         // + ks*32
    const int b_row_l = wn * 32 + (lane >> 4) * 8 + (lane & 7);   // + p*16
    const int b_colb  = ((lane >> 3) & 1) * 16;                   // + ks*32

    for (int c = 0; c < NCHUNK; c++) {
        if (c == NCHUNK - 1) { CP_WAIT(0); } else { CP_WAIT(1); }
        __syncthreads();

        uint32_t Ab = sbase + (c & 1) * STAGE_BYTES;
        uint32_t Bb = Ab + A_STAGE_BYTES;

#pragma unroll
        for (int ks = 0; ks < 4; ks++) {
            uint32_t af[4][4], bf[2][4];
#pragma unroll
            for (int mt = 0; mt < 4; mt++) {
                int row = a_row_l + mt * 16;
                ldsm_x4(af[mt][0], af[mt][1], af[mt][2], af[mt][3],
                        Ab + swz(row, ks * 32 + a_colb));
            }
#pragma unroll
            for (int p = 0; p < 2; p++) {        // pair p covers n-tiles 2p,2p+1
                int row = b_row_l + p * 16;
                ldsm_x4(bf[p][0], bf[p][1], bf[p][2], bf[p][3],
                        Bb + swz(row, ks * 32 + b_colb));
            }
#pragma unroll
            for (int mt = 0; mt < 4; mt++)
#pragma unroll
                for (int nt = 0; nt < 4; nt++)
                    mma_bf16(acc[mt][nt], af[mt], &bf[nt >> 1][(nt & 1) * 2]);
        }

        __syncthreads();
        if (c + 2 < NCHUNK) { load_stage(c + 2, c & 1); CP_COMMIT(); }
    }

    // ---------------- epilogue ----------------
    // acc frag c0,c1: (row lane/4,     col 2(lane%4), +1)
    //          c2,c3: (row lane/4 + 8, col 2(lane%4), +1)
    const int er = lane >> 2;
    const int ec = 2 * (lane & 3);
    const float* X2 = g_X2 + b * NROWS + i0 + wm * 64;
    const float* Y2 = g_Y2 + b * NROWS + j0 + wn * 32;

#pragma unroll
    for (int mt = 0; mt < 4; mt++) {
        float x2a = X2[mt * 16 + er];
        float x2b = X2[mt * 16 + er + 8];
#pragma unroll
        for (int nt = 0; nt < 4; nt++) {
            float2 y2 = *(const float2*)(Y2 + nt * 8 + ec);
            float* a = acc[mt][nt];

            float d0 = fmaxf(x2a + y2.x - 2.f * a[0], 0.f);
            float d1 = fmaxf(x2a + y2.y - 2.f * a[1], 0.f);
            float d2 = fmaxf(x2b + y2.x - 2.f * a[2], 0.f);
            float d3 = fmaxf(x2b + y2.y - 2.f * a[3], 0.f);

            float2 o01, o23;
            o01.x = (d0 < 212.f) ? __expf(-0.5f * d0) : 0.f;
            o01.y = (d1 < 212.f) ? __expf(-0.5f * d1) : 0.f;
            o23.x = (d2 < 212.f) ? __expf(-0.5f * d2) : 0.f;
            o23.y = (d3 < 212.f) ? __expf(-0.5f * d3) : 0.f;

            size_t r0 = (size_t)(b * NROWS + i0 + wm * 64 + mt * 16 + er) * NROWS
                        + j0 + wn * 32 + nt * 8 + ec;
            *(float2*)(out + r0) = o01;
            *(float2*)(out + r0 + 8 * NROWS) = o23;
        }
    }
}

extern "C" void kernel_launch(void* const* d_in, const int* in_sizes, int n_in,
                              void* d_out, int out_size) {
    const float* X = (const float*)d_in[0];
    const float* Y = (const float*)d_in[1];
    float* out = (float*)d_out;

    cudaFuncSetAttribute(rbf_mma, cudaFuncAttributeMaxDynamicSharedMemorySize, SMEM_BYTES);

    rbf_prep<<<2 * BATCH * NROWS / 8, 256>>>(X, Y);

    dim3 grid(NROWS / BN, NROWS / BM, BATCH);   // (16, 32, 4)
    rbf_mma<<<grid, THREADS, SMEM_BYTES>>>(out);
}